// round 9
// baseline (speedup 1.0000x reference)
#include <cuda_runtime.h>
#include <cuda_bf16.h>
#include <math.h>

// ---------------------------------------------------------------------------
// weighted_loss: graph neighbor-state histogram weighted cross entropy
//   s0[i] = #neighbors with x==1, s1[i] = #neighbors with x==0 (per dst row)
//   counts[i] = multiplicity of key (x[i], s0[i], s1[i])
//   w = counts^-0.5 ; result = sum(nll*w)/sum(w)
// ---------------------------------------------------------------------------

#define NMAX    262144
#define NWMAX   8192            // bitmask words (N/32 = 6250 actual)
#define KEYBITS 17              // 1 (x) + 8 (s0) + 8 (s1)
#define HSIZE   (1 << KEYBITS)  // 128k entries, 512 KB

__device__ unsigned g_s[NMAX];      // packed: hi16 = #x==1 nbrs, lo16 = #x==0 nbrs
__device__ unsigned g_xbits[NWMAX];
__device__ int      g_hist[HSIZE];
__device__ float    g_acc[2];       // [0] = sum_w, [1] = sum_nll_w

// ---------------------------------------------------------------------------
// Fused init: zero hist + s, pack x into bitmask, reset accumulators.
__global__ void k_init(const int* __restrict__ x, int n_nodes, int nbits) {
    int tid = blockIdx.x * blockDim.x + threadIdx.x;
    int stride = gridDim.x * blockDim.x;

    int4* h4 = reinterpret_cast<int4*>(g_hist);
    const int4 z4 = make_int4(0, 0, 0, 0);
    for (int j = tid; j < HSIZE / 4; j += stride) h4[j] = z4;
    for (int j = tid; j < n_nodes; j += stride) g_s[j] = 0u;

    for (int t = tid; t < nbits; t += stride) {
        int xi = (t < n_nodes) ? x[t] : 0;
        unsigned m = __ballot_sync(0xFFFFFFFFu, xi > 0);
        if ((t & 31) == 0) g_xbits[t >> 5] = m;
    }
    if (tid == 0) { g_acc[0] = 0.0f; g_acc[1] = 0.0f; }
}

// ---------------------------------------------------------------------------
// Persistent edge kernel: smem x-bitmask, streaming int4 loads, 8 edges/iter,
// branchless packed RED per edge.
#define EDGE_T 256
__device__ __forceinline__ unsigned inc_of(const unsigned* sbits, int c) {
    unsigned b = (sbits[c >> 5] >> (c & 31)) & 1u;
    return 1u + b * 0xFFFFu;        // 1 if x==0, 0x10000 if x==1
}

__global__ void __launch_bounds__(EDGE_T) k_edges(
        const int* __restrict__ row,
        const int* __restrict__ col,
        int nwords, int E8, int E) {
    __shared__ unsigned sbits[NWMAX];
    for (int j = threadIdx.x; j < nwords; j += EDGE_T)
        sbits[j] = g_xbits[j];
    __syncthreads();

    const int4* __restrict__ r4 = reinterpret_cast<const int4*>(row);
    const int4* __restrict__ c4 = reinterpret_cast<const int4*>(col);
    int tid = blockIdx.x * EDGE_T + threadIdx.x;
    int gstride = gridDim.x * EDGE_T;

    for (int i = tid; i < E8; i += gstride) {
        int4 ra = __ldcs(&r4[2 * i]);
        int4 rb = __ldcs(&r4[2 * i + 1]);
        int4 ca = __ldcs(&c4[2 * i]);
        int4 cb = __ldcs(&c4[2 * i + 1]);
        unsigned v0 = inc_of(sbits, ca.x);
        unsigned v1 = inc_of(sbits, ca.y);
        unsigned v2 = inc_of(sbits, ca.z);
        unsigned v3 = inc_of(sbits, ca.w);
        unsigned v4 = inc_of(sbits, cb.x);
        unsigned v5 = inc_of(sbits, cb.y);
        unsigned v6 = inc_of(sbits, cb.z);
        unsigned v7 = inc_of(sbits, cb.w);
        atomicAdd(&g_s[ra.x], v0);
        atomicAdd(&g_s[ra.y], v1);
        atomicAdd(&g_s[ra.z], v2);
        atomicAdd(&g_s[ra.w], v3);
        atomicAdd(&g_s[rb.x], v4);
        atomicAdd(&g_s[rb.y], v5);
        atomicAdd(&g_s[rb.z], v6);
        atomicAdd(&g_s[rb.w], v7);
    }
    // tail (E % 8)
    if (tid == 0) {
        for (int e = E8 * 8; e < E; ++e) {
            atomicAdd(&g_s[row[e]], inc_of(sbits, col[e]));
        }
    }
}

// ---------------------------------------------------------------------------
__device__ __forceinline__ unsigned node_key(unsigned xb, unsigned s) {
    unsigned s0 = s >> 16;
    unsigned s1 = s & 0xFFFFu;
    s0 = (s0 > 255u) ? 255u : s0;
    s1 = (s1 > 255u) ? 255u : s1;
    return (xb << 16) | (s0 << 8) | s1;
}

// 4 nodes per thread for memory-level parallelism.
__global__ void k_keys(int n4, int n_nodes) {
    int i = blockIdx.x * blockDim.x + threadIdx.x;
    if (i < n4) {
        int j = 4 * i;
        uint4 sv = reinterpret_cast<const uint4*>(g_s)[i];
        unsigned bits = (g_xbits[j >> 5] >> (j & 31)) & 0xFu;  // j % 4 == 0
        atomicAdd(&g_hist[node_key(bits & 1u, sv.x)], 1);
        atomicAdd(&g_hist[node_key((bits >> 1) & 1u, sv.y)], 1);
        atomicAdd(&g_hist[node_key((bits >> 2) & 1u, sv.z)], 1);
        atomicAdd(&g_hist[node_key((bits >> 3) & 1u, sv.w)], 1);
    }
    if (i == 0) {
        for (int j = n4 * 4; j < n_nodes; ++j) {
            unsigned xb = (g_xbits[j >> 5] >> (j & 31)) & 1u;
            atomicAdd(&g_hist[node_key(xb, g_s[j])], 1);
        }
    }
}

// ---------------------------------------------------------------------------
// 4 nodes per thread; warp + block reduce; two float atomics per block.
__global__ void __launch_bounds__(256) k_loss(const float* __restrict__ out2,
                                              const int* __restrict__ y,
                                              int n4, int n_nodes) {
    __shared__ float sh_w[8];
    __shared__ float sh_nw[8];
    int i = blockIdx.x * blockDim.x + threadIdx.x;
    float w = 0.0f, nw = 0.0f;
    if (i < n4) {
        int j = 4 * i;
        uint4 sv = reinterpret_cast<const uint4*>(g_s)[i];
        int4  yv = reinterpret_cast<const int4*>(y)[i];
        float4 oa = reinterpret_cast<const float4*>(out2)[2 * i];
        float4 ob = reinterpret_cast<const float4*>(out2)[2 * i + 1];
        unsigned bits = (g_xbits[j >> 5] >> (j & 31)) & 0xFu;
        int c0 = g_hist[node_key(bits & 1u, sv.x)];
        int c1 = g_hist[node_key((bits >> 1) & 1u, sv.y)];
        int c2 = g_hist[node_key((bits >> 2) & 1u, sv.z)];
        int c3 = g_hist[node_key((bits >> 3) & 1u, sv.w)];

        float aa[4] = {oa.x, oa.z, ob.x, ob.z};
        float bb[4] = {oa.y, oa.w, ob.y, ob.w};
        int   yy[4] = {yv.x, yv.y, yv.z, yv.w};
        int   cc[4] = {c0, c1, c2, c3};
        #pragma unroll
        for (int u = 0; u < 4; ++u) {
            float wi = rsqrtf((float)cc[u]);
            float m = fmaxf(aa[u], bb[u]);
            float lse = m + logf(expf(aa[u] - m) + expf(bb[u] - m));
            float sel = (yy[u] == 0) ? aa[u] : bb[u];
            w  += wi;
            nw += (lse - sel) * wi;
        }
    } else if (i == n4) {
        for (int j = n4 * 4; j < n_nodes; ++j) {
            unsigned xb = (g_xbits[j >> 5] >> (j & 31)) & 1u;
            float wi = rsqrtf((float)g_hist[node_key(xb, g_s[j])]);
            float a = out2[2 * j], b = out2[2 * j + 1];
            float m = fmaxf(a, b);
            float lse = m + logf(expf(a - m) + expf(b - m));
            float sel = (y[j] == 0) ? a : b;
            w  += wi;
            nw += (lse - sel) * wi;
        }
    }
    #pragma unroll
    for (int off = 16; off > 0; off >>= 1) {
        w  += __shfl_down_sync(0xFFFFFFFFu, w,  off);
        nw += __shfl_down_sync(0xFFFFFFFFu, nw, off);
    }
    int lane = threadIdx.x & 31, warp = threadIdx.x >> 5;
    if (lane == 0) { sh_w[warp] = w; sh_nw[warp] = nw; }
    __syncthreads();
    if (warp == 0) {
        w  = (lane < 8) ? sh_w[lane]  : 0.0f;
        nw = (lane < 8) ? sh_nw[lane] : 0.0f;
        #pragma unroll
        for (int off = 4; off > 0; off >>= 1) {
            w  += __shfl_down_sync(0xFFu, w,  off);
            nw += __shfl_down_sync(0xFFu, nw, off);
        }
        if (lane == 0) {
            atomicAdd(&g_acc[0], w);
            atomicAdd(&g_acc[1], nw);
        }
    }
}

// ---------------------------------------------------------------------------
__global__ void k_final(float* __restrict__ out) {
    out[0] = g_acc[1] / g_acc[0];
}

// ---------------------------------------------------------------------------
extern "C" void kernel_launch(void* const* d_in, const int* in_sizes, int n_in,
                              void* d_out, int out_size) {
    const float* out2 = (const float*)d_in[0];   // (N, 2) logits
    const int*   x    = (const int*)d_in[1];     // (N,) binary feature
    const int*   y    = (const int*)d_in[2];     // (N,) labels
    const int*   ei   = (const int*)d_in[3];     // (2, E) row-major
    float*       res  = (float*)d_out;

    const int N = in_sizes[1];
    const int E = in_sizes[3] / 2;
    const int* row = ei;
    const int* col = ei + E;

    const int nwords = (N + 31) / 32;
    const int nbits  = nwords * 32;

    // 1) fused init (zero hist/s, pack x bits)
    k_init<<<1024, 256>>>(x, N, nbits);

    // 2) edge scatter: persistent blocks, smem bitmask
    int E8 = E / 8;
    k_edges<<<592, EDGE_T>>>(row, col, nwords, E8, E);

    // 3) key histogram (4 nodes/thread)
    int n4 = N / 4;
    int nb = (n4 + 255) / 256;
    k_keys<<<nb, 256>>>(n4, N);

    // 4) weighted loss partial sums (4 nodes/thread)
    int nb2 = (n4 + 1 + 255) / 256;   // +1 thread for the tail
    k_loss<<<nb2, 256>>>(out2, y, n4, N);

    // 5) final scalar
    k_final<<<1, 1>>>(res);
}